// round 9
// baseline (speedup 1.0000x reference)
#include <cuda_runtime.h>
#include <cuda_bf16.h>

// Problem constants
#define BB 4
#define LL 2048
#define DM 1024
#define NH 16
#define DH 64
#define MD 128          // MAX_DIST
#define NBIAS 257       // 2*MD+1

// Scratch (device globals: allocation-free rule)
__device__ float g_Q[BB * NH * LL * DH];   // [b,h,l,d]
__device__ float g_K[BB * NH * LL * DH];
__device__ float g_V[BB * NH * LL * DH];
__device__ float g_AO[BB * LL * DM];       // attention out, [b,l,h*64+d]

// ---------------------------------------------------------------------------
// GEMM 1 (UNCHANGED from round-2 passing kernel):
// qkv = x @ Wqkv + bqkv, scattered into g_Q/g_K/g_V head layout.
// ---------------------------------------------------------------------------
__global__ __launch_bounds__(256) void qkv_gemm(
    const float* __restrict__ X, const float* __restrict__ W,
    const float* __restrict__ bias) {
    __shared__ float As[16][132];
    __shared__ float Bs[16][128];

    const int tid = threadIdx.x;
    const int tx = tid & 15, ty = tid >> 4;
    const int m0 = blockIdx.y * 128, n0 = blockIdx.x * 128;

    float acc[8][8];
#pragma unroll
    for (int i = 0; i < 8; i++)
#pragma unroll
        for (int j = 0; j < 8; j++) acc[i][j] = 0.f;

    for (int k0 = 0; k0 < 1024; k0 += 16) {
#pragma unroll
        for (int r = 0; r < 2; r++) {
            int i = tid + r * 256;
            int row = i >> 2, c4 = i & 3;
            float4 v = *(const float4*)&X[(size_t)(m0 + row) * 1024 + k0 + c4 * 4];
            As[c4 * 4 + 0][row] = v.x;
            As[c4 * 4 + 1][row] = v.y;
            As[c4 * 4 + 2][row] = v.z;
            As[c4 * 4 + 3][row] = v.w;
        }
#pragma unroll
        for (int r = 0; r < 2; r++) {
            int i = tid + r * 256;
            int row = i >> 5, c4 = i & 31;
            float4 v = *(const float4*)&W[(size_t)(k0 + row) * 3072 + n0 + c4 * 4];
            *(float4*)&Bs[row][c4 * 4] = v;
        }
        __syncthreads();

#pragma unroll
        for (int kk = 0; kk < 16; kk++) {
            float4 a0 = *(const float4*)&As[kk][ty * 4];
            float4 a1 = *(const float4*)&As[kk][64 + ty * 4];
            float4 b0 = *(const float4*)&Bs[kk][tx * 4];
            float4 b1 = *(const float4*)&Bs[kk][64 + tx * 4];
            float a[8] = {a0.x, a0.y, a0.z, a0.w, a1.x, a1.y, a1.z, a1.w};
            float b[8] = {b0.x, b0.y, b0.z, b0.w, b1.x, b1.y, b1.z, b1.w};
#pragma unroll
            for (int i = 0; i < 8; i++)
#pragma unroll
                for (int j = 0; j < 8; j++) acc[i][j] += a[i] * b[j];
        }
        __syncthreads();
    }

#pragma unroll
    for (int i = 0; i < 8; i++) {
        int m = m0 + ((i < 4) ? (ty * 4 + i) : (64 + ty * 4 + i - 4));
        int b = m >> 11, l = m & 2047;
#pragma unroll
        for (int jh = 0; jh < 2; jh++) {
            int n = n0 + jh * 64 + tx * 4;
            float4 v;
            v.x = acc[i][jh * 4 + 0] + bias[n + 0];
            v.y = acc[i][jh * 4 + 1] + bias[n + 1];
            v.z = acc[i][jh * 4 + 2] + bias[n + 2];
            v.w = acc[i][jh * 4 + 3] + bias[n + 3];
            int which = n >> 10;
            int nn = n & 1023;
            int h = nn >> 6, d = nn & 63;
            float* dst = (which == 0) ? g_Q : (which == 1) ? g_K : g_V;
            *(float4*)&dst[((size_t)(b * NH + h) * LL + l) * DH + d] = v;
        }
    }
}

// ---------------------------------------------------------------------------
// Attention v3: q-tile 128, 256 threads, 8x4 micro-tiles, softmax fused into
// the S register phase (shfl reductions within 16-lane tx groups).
// Per tile: sync(load) -> S+softmax+P-store -> syncwarp -> PV -> sync.
// ---------------------------------------------------------------------------
#define QT 128              // q rows per block
#define QPAD 132            // padded q stride
#define KPAD 68             // padded k/d stride
#define ATTN_SMEM_FLOATS (64 * QPAD + 64 * KPAD + 64 * KPAD + 64 * QPAD + \
                          NBIAS + 2 * QT + 64)

__global__ __launch_bounds__(256) void attn_kernel(
    const int* __restrict__ mask, const float* __restrict__ rel_bias) {
    extern __shared__ float sm[];
    float* Qs = sm;                          // [d=64][q=128] (+pad)
    float* Ks = Qs + 64 * QPAD;              // [d=64][k=64]  (+pad)
    float* Vs = Ks + 64 * KPAD;              // [k=64][d=64]  (+pad)
    float* Ss = Vs + 64 * KPAD;              // [k=64][q=128] (+pad)  P
    float* bias_s = Ss + 64 * QPAD;          // 257
    float* row_m = bias_s + NBIAS;           // 128
    float* row_l = row_m + QT;               // 128
    float* maskf = row_l + QT;               // 64

    const int tid = threadIdx.x;
    const int tx = tid & 15, ty = tid >> 4;  // tx: k/d quad, ty: q octet
    const int bh = blockIdx.y;
    const int b = bh / NH, h = bh % NH;
    const int q0 = blockIdx.x * QT;

    for (int i = tid; i < NBIAS; i += 256) bias_s[i] = rel_bias[h * NBIAS + i];
    if (tid < QT) { row_m[tid] = -1e30f; row_l[tid] = 0.f; }

    // Q tile transposed -> Qs[d][q], scale folded
    const float* Qg = g_Q + ((size_t)bh * LL + q0) * DH;
#pragma unroll
    for (int r = 0; r < 8; r++) {
        int i = tid + r * 256;               // 0..2047 float4s
        int q = i >> 4, d4 = i & 15;
        float4 v = *(const float4*)&Qg[q * DH + d4 * 4];
        Qs[(d4 * 4 + 0) * QPAD + q] = v.x * 0.125f;
        Qs[(d4 * 4 + 1) * QPAD + q] = v.y * 0.125f;
        Qs[(d4 * 4 + 2) * QPAD + q] = v.z * 0.125f;
        Qs[(d4 * 4 + 3) * QPAD + q] = v.w * 0.125f;
    }

    float o[8][4];
#pragma unroll
    for (int i = 0; i < 8; i++)
#pragma unroll
        for (int j = 0; j < 4; j++) o[i][j] = 0.f;

    __syncthreads();

    for (int kt = 0; kt < LL / 64; kt++) {
        const int k0 = kt * 64;
        const float* Kg = g_K + ((size_t)bh * LL + k0) * DH;
        const float* Vg = g_V + ((size_t)bh * LL + k0) * DH;
        // K transposed -> Ks[d][k]; V direct -> Vs[k][d]
#pragma unroll
        for (int r = 0; r < 4; r++) {
            int i = tid + r * 256;           // 0..1023 float4s
            int kq = i >> 4, d4 = i & 15;
            float4 v = *(const float4*)&Kg[kq * DH + d4 * 4];
            Ks[(d4 * 4 + 0) * KPAD + kq] = v.x;
            Ks[(d4 * 4 + 1) * KPAD + kq] = v.y;
            Ks[(d4 * 4 + 2) * KPAD + kq] = v.z;
            Ks[(d4 * 4 + 3) * KPAD + kq] = v.w;
            float4 w = *(const float4*)&Vg[kq * DH + d4 * 4];
            *(float4*)&Vs[kq * KPAD + d4 * 4] = w;
        }
        if (tid < 64) maskf[tid] = (mask[b * LL + k0 + tid] != 0) ? 0.f : -1e30f;
        __syncthreads();

        // ---- S = Q K^T : thread (ty,tx) -> q rows ty*8..+7, k cols tx*4..+3
        float s[8][4];
#pragma unroll
        for (int i = 0; i < 8; i++)
#pragma unroll
            for (int j = 0; j < 4; j++) s[i][j] = 0.f;
#pragma unroll
        for (int kk = 0; kk < 64; kk++) {
            float4 a0 = *(const float4*)&Qs[kk * QPAD + ty * 8];
            float4 a1 = *(const float4*)&Qs[kk * QPAD + ty * 8 + 4];
            float4 bv = *(const float4*)&Ks[kk * KPAD + tx * 4];
            float a[8] = {a0.x, a0.y, a0.z, a0.w, a1.x, a1.y, a1.z, a1.w};
            float bb[4] = {bv.x, bv.y, bv.z, bv.w};
#pragma unroll
            for (int i = 0; i < 8; i++)
#pragma unroll
                for (int j = 0; j < 4; j++) s[i][j] += a[i] * bb[j];
        }

        // ---- fused bias + mask + streaming softmax (registers + shfl) ----
        const float mk0 = maskf[tx * 4 + 0], mk1 = maskf[tx * 4 + 1];
        const float mk2 = maskf[tx * 4 + 2], mk3 = maskf[tx * 4 + 3];
#pragma unroll
        for (int i = 0; i < 8; i++) {
            const int q = ty * 8 + i;
            const int qg = q0 + q;
            const int kg = k0 + tx * 4;
            int r0 = kg - qg;     r0 = r0 < -MD ? -MD : (r0 > MD ? MD : r0);
            int r1 = kg + 1 - qg; r1 = r1 < -MD ? -MD : (r1 > MD ? MD : r1);
            int r2 = kg + 2 - qg; r2 = r2 < -MD ? -MD : (r2 > MD ? MD : r2);
            int r3 = kg + 3 - qg; r3 = r3 < -MD ? -MD : (r3 > MD ? MD : r3);
            s[i][0] += bias_s[r0 + MD] + mk0;
            s[i][1] += bias_s[r1 + MD] + mk1;
            s[i][2] += bias_s[r2 + MD] + mk2;
            s[i][3] += bias_s[r3 + MD] + mk3;

            float mx = fmaxf(fmaxf(s[i][0], s[i][1]), fmaxf(s[i][2], s[i][3]));
            mx = fmaxf(mx, __shfl_xor_sync(0xffffffffu, mx, 1));
            mx = fmaxf(mx, __shfl_xor_sync(0xffffffffu, mx, 2));
            mx = fmaxf(mx, __shfl_xor_sync(0xffffffffu, mx, 4));
            mx = fmaxf(mx, __shfl_xor_sync(0xffffffffu, mx, 8));

            const float mold = row_m[q];
            const float mnew = fmaxf(mold, mx);
            const float f = __expf(mold - mnew);
            s[i][0] = __expf(s[i][0] - mnew);
            s[i][1] = __expf(s[i][1] - mnew);
            s[i][2] = __expf(s[i][2] - mnew);
            s[i][3] = __expf(s[i][3] - mnew);
            float sum = (s[i][0] + s[i][1]) + (s[i][2] + s[i][3]);
            sum += __shfl_xor_sync(0xffffffffu, sum, 1);
            sum += __shfl_xor_sync(0xffffffffu, sum, 2);
            sum += __shfl_xor_sync(0xffffffffu, sum, 4);
            sum += __shfl_xor_sync(0xffffffffu, sum, 8);
            if (tx == 0) {
                row_m[q] = mnew;
                row_l[q] = row_l[q] * f + sum;
            }
            // rescale O row by f (every lane has f)
            o[i][0] *= f; o[i][1] *= f; o[i][2] *= f; o[i][3] *= f;
        }

        // store P transposed: Ss[k][q] (consumed only by this half-warp)
#pragma unroll
        for (int j = 0; j < 4; j++) {
            float* dst = &Ss[(tx * 4 + j) * QPAD + ty * 8];
            *(float4*)&dst[0] = make_float4(s[0][j], s[1][j], s[2][j], s[3][j]);
            *(float4*)&dst[4] = make_float4(s[4][j], s[5][j], s[6][j], s[7][j]);
        }
        __syncwarp();   // P produced/consumed within the same warp

        // ---- O += P V : P = Ss[k][q], V = Vs[k][d] ----
#pragma unroll
        for (int kk = 0; kk < 64; kk++) {
            float4 p0 = *(const float4*)&Ss[kk * QPAD + ty * 8];
            float4 p1 = *(const float4*)&Ss[kk * QPAD + ty * 8 + 4];
            float4 vv = *(const float4*)&Vs[kk * KPAD + tx * 4];
            float p[8] = {p0.x, p0.y, p0.z, p0.w, p1.x, p1.y, p1.z, p1.w};
#pragma unroll
            for (int i = 0; i < 8; i++) {
                o[i][0] += p[i] * vv.x;
                o[i][1] += p[i] * vv.y;
                o[i][2] += p[i] * vv.z;
                o[i][3] += p[i] * vv.w;
            }
        }
        __syncthreads();   // before next tile overwrites Ks/Vs
    }

    // epilogue: normalize, write [b, l, h*64+d]
#pragma unroll
    for (int i = 0; i < 8; i++) {
        const int q = ty * 8 + i;
        const float inv = 1.f / row_l[q];
        const int qg = q0 + q;
        *(float4*)&g_AO[((size_t)b * LL + qg) * DM + h * DH + tx * 4] =
            make_float4(o[i][0] * inv, o[i][1] * inv,
                        o[i][2] * inv, o[i][3] * inv);
    }
}

// ---------------------------------------------------------------------------
// GEMM 2 (UNCHANGED from round-2 passing kernel): out = AO @ Wo + bo.
// ---------------------------------------------------------------------------
__global__ __launch_bounds__(256) void out_gemm(
    const float* __restrict__ W, const float* __restrict__ bias,
    float* __restrict__ out) {
    __shared__ float As[16][132];
    __shared__ float Bs[16][128];

    const int tid = threadIdx.x;
    const int tx = tid & 15, ty = tid >> 4;
    const int m0 = blockIdx.y * 128, n0 = blockIdx.x * 128;
    const float* A = g_AO;

    float acc[8][8];
#pragma unroll
    for (int i = 0; i < 8; i++)
#pragma unroll
        for (int j = 0; j < 8; j++) acc[i][j] = 0.f;

    for (int k0 = 0; k0 < 1024; k0 += 16) {
#pragma unroll
        for (int r = 0; r < 2; r++) {
            int i = tid + r * 256;
            int row = i >> 2, c4 = i & 3;
            float4 v = *(const float4*)&A[(size_t)(m0 + row) * 1024 + k0 + c4 * 4];
            As[c4 * 4 + 0][row] = v.x;
            As[c4 * 4 + 1][row] = v.y;
            As[c4 * 4 + 2][row] = v.z;
            As[c4 * 4 + 3][row] = v.w;
        }
#pragma unroll
        for (int r = 0; r < 2; r++) {
            int i = tid + r * 256;
            int row = i >> 5, c4 = i & 31;
            float4 v = *(const float4*)&W[(size_t)(k0 + row) * 1024 + n0 + c4 * 4];
            *(float4*)&Bs[row][c4 * 4] = v;
        }
        __syncthreads();
#pragma unroll
        for (int kk = 0; kk < 16; kk++) {
            float4 a0 = *(const float4*)&As[kk][ty * 4];
            float4 a1 = *(const float4*)&As[kk][64 + ty * 4];
            float4 b0 = *(const float4*)&Bs[kk][tx * 4];
            float4 b1 = *(const float4*)&Bs[kk][64 + tx * 4];
            float a[8] = {a0.x, a0.y, a0.z, a0.w, a1.x, a1.y, a1.z, a1.w};
            float b[8] = {b0.x, b0.y, b0.z, b0.w, b1.x, b1.y, b1.z, b1.w};
#pragma unroll
            for (int i = 0; i < 8; i++)
#pragma unroll
                for (int j = 0; j < 8; j++) acc[i][j] += a[i] * b[j];
        }
        __syncthreads();
    }

#pragma unroll
    for (int i = 0; i < 8; i++) {
        int m = m0 + ((i < 4) ? (ty * 4 + i) : (64 + ty * 4 + i - 4));
#pragma unroll
        for (int jh = 0; jh < 2; jh++) {
            int n = n0 + jh * 64 + tx * 4;
            float4 v;
            v.x = acc[i][jh * 4 + 0] + bias[n + 0];
            v.y = acc[i][jh * 4 + 1] + bias[n + 1];
            v.z = acc[i][jh * 4 + 2] + bias[n + 2];
            v.w = acc[i][jh * 4 + 3] + bias[n + 3];
            *(float4*)&out[(size_t)m * 1024 + n] = v;
        }
    }
}

// ---------------------------------------------------------------------------
extern "C" void kernel_launch(void* const* d_in, const int* in_sizes, int n_in,
                              void* d_out, int out_size) {
    const float* x    = (const float*)d_in[0];
    const int* mask   = (const int*)d_in[1];      // bool -> int32 in harness
    const float* Wqkv = (const float*)d_in[2];
    const float* bqkv = (const float*)d_in[3];
    const float* Wo   = (const float*)d_in[4];
    const float* bo   = (const float*)d_in[5];
    const float* rb   = (const float*)d_in[6];
    float* out        = (float*)d_out;

    qkv_gemm<<<dim3(3072 / 128, 8192 / 128), 256>>>(x, Wqkv, bqkv);

    const int smem_bytes = ATTN_SMEM_FLOATS * (int)sizeof(float);
    cudaFuncSetAttribute(attn_kernel,
                         cudaFuncAttributeMaxDynamicSharedMemorySize, smem_bytes);
    attn_kernel<<<dim3(LL / QT, BB * NH), 256, smem_bytes>>>(mask, rb);

    out_gemm<<<dim3(1024 / 128, 8192 / 128), 256>>>(Wo, bo, out);
}

// round 10
// speedup vs baseline: 1.0088x; 1.0088x over previous
#include <cuda_runtime.h>
#include <cuda_bf16.h>

// Problem constants
#define BB 4
#define LL 2048
#define DM 1024
#define NH 16
#define DH 64
#define MD 128          // MAX_DIST
#define NBIAS 257       // 2*MD+1

// Scratch (device globals: allocation-free rule)
__device__ float g_Q[BB * NH * LL * DH];   // [b,h,l,d]
__device__ float g_K[BB * NH * LL * DH];
__device__ float g_V[BB * NH * LL * DH];
__device__ float g_AO[BB * LL * DM];       // attention out, [b,l,h*64+d]

// ---------------------------------------------------------------------------
// GEMM 1 (UNCHANGED from round-2 passing kernel):
// qkv = x @ Wqkv + bqkv, scattered into g_Q/g_K/g_V head layout.
// ---------------------------------------------------------------------------
__global__ __launch_bounds__(256) void qkv_gemm(
    const float* __restrict__ X, const float* __restrict__ W,
    const float* __restrict__ bias) {
    __shared__ float As[16][132];
    __shared__ float Bs[16][128];

    const int tid = threadIdx.x;
    const int tx = tid & 15, ty = tid >> 4;
    const int m0 = blockIdx.y * 128, n0 = blockIdx.x * 128;

    float acc[8][8];
#pragma unroll
    for (int i = 0; i < 8; i++)
#pragma unroll
        for (int j = 0; j < 8; j++) acc[i][j] = 0.f;

    for (int k0 = 0; k0 < 1024; k0 += 16) {
#pragma unroll
        for (int r = 0; r < 2; r++) {
            int i = tid + r * 256;
            int row = i >> 2, c4 = i & 3;
            float4 v = *(const float4*)&X[(size_t)(m0 + row) * 1024 + k0 + c4 * 4];
            As[c4 * 4 + 0][row] = v.x;
            As[c4 * 4 + 1][row] = v.y;
            As[c4 * 4 + 2][row] = v.z;
            As[c4 * 4 + 3][row] = v.w;
        }
#pragma unroll
        for (int r = 0; r < 2; r++) {
            int i = tid + r * 256;
            int row = i >> 5, c4 = i & 31;
            float4 v = *(const float4*)&W[(size_t)(k0 + row) * 3072 + n0 + c4 * 4];
            *(float4*)&Bs[row][c4 * 4] = v;
        }
        __syncthreads();

#pragma unroll
        for (int kk = 0; kk < 16; kk++) {
            float4 a0 = *(const float4*)&As[kk][ty * 4];
            float4 a1 = *(const float4*)&As[kk][64 + ty * 4];
            float4 b0 = *(const float4*)&Bs[kk][tx * 4];
            float4 b1 = *(const float4*)&Bs[kk][64 + tx * 4];
            float a[8] = {a0.x, a0.y, a0.z, a0.w, a1.x, a1.y, a1.z, a1.w};
            float b[8] = {b0.x, b0.y, b0.z, b0.w, b1.x, b1.y, b1.z, b1.w};
#pragma unroll
            for (int i = 0; i < 8; i++)
#pragma unroll
                for (int j = 0; j < 8; j++) acc[i][j] += a[i] * b[j];
        }
        __syncthreads();
    }

#pragma unroll
    for (int i = 0; i < 8; i++) {
        int m = m0 + ((i < 4) ? (ty * 4 + i) : (64 + ty * 4 + i - 4));
        int b = m >> 11, l = m & 2047;
#pragma unroll
        for (int jh = 0; jh < 2; jh++) {
            int n = n0 + jh * 64 + tx * 4;
            float4 v;
            v.x = acc[i][jh * 4 + 0] + bias[n + 0];
            v.y = acc[i][jh * 4 + 1] + bias[n + 1];
            v.z = acc[i][jh * 4 + 2] + bias[n + 2];
            v.w = acc[i][jh * 4 + 3] + bias[n + 3];
            int which = n >> 10;
            int nn = n & 1023;
            int h = nn >> 6, d = nn & 63;
            float* dst = (which == 0) ? g_Q : (which == 1) ? g_K : g_V;
            *(float4*)&dst[((size_t)(b * NH + h) * LL + l) * DH + d] = v;
        }
    }
}

// ---------------------------------------------------------------------------
// Attention v4 = R8 structure + swizzled smem layouts for K/V/S tiles.
// Rotation is a function of (row, col) only; store and read sides match.
//   Ks[d][k]:  k-granule g stored at (g + (d>>2)) & 15
//   Vs[k][d]:  d-granule g stored at (g + (k>>2)) & 15
//   Ss[k][q]:  q-granule g stored at (g + (k>>2)) & 31
// ---------------------------------------------------------------------------
#define QT 128              // q rows per block
#define QPAD 132            // padded q stride
#define KPAD 68             // padded k/d stride
#define ATTN_SMEM_FLOATS (64 * QPAD + 64 * KPAD + 64 * KPAD + 64 * QPAD + \
                          NBIAS + 3 * QT + 64)

__global__ __launch_bounds__(256) void attn_kernel(
    const int* __restrict__ mask, const float* __restrict__ rel_bias) {
    extern __shared__ float sm[];
    float* Qs = sm;                          // [d=64][q=128] (+pad)
    float* Ks = Qs + 64 * QPAD;              // [d=64][k=64]  (+pad, swizzled)
    float* Vs = Ks + 64 * KPAD;              // [k=64][d=64]  (+pad, swizzled)
    float* Ss = Vs + 64 * KPAD;              // [k=64][q=128] (+pad, swizzled)
    float* bias_s = Ss + 64 * QPAD;          // 257
    float* row_m = bias_s + NBIAS;           // 128
    float* row_l = row_m + QT;               // 128
    float* row_f = row_l + QT;               // 128
    float* maskf = row_f + QT;               // 64

    const int tid = threadIdx.x;
    const int tx = tid & 15, ty = tid >> 4;  // tx: k/d quad, ty: q octet
    const int bh = blockIdx.y;
    const int b = bh / NH, h = bh % NH;
    const int q0 = blockIdx.x * QT;

    for (int i = tid; i < NBIAS; i += 256) bias_s[i] = rel_bias[h * NBIAS + i];
    if (tid < QT) { row_m[tid] = -1e30f; row_l[tid] = 0.f; }

    // Q tile transposed -> Qs[d][q], scale folded (unswizzled; loaded once)
    const float* Qg = g_Q + ((size_t)bh * LL + q0) * DH;
#pragma unroll
    for (int r = 0; r < 8; r++) {
        int i = tid + r * 256;               // 0..2047 float4s
        int q = i >> 4, d4 = i & 15;
        float4 v = *(const float4*)&Qg[q * DH + d4 * 4];
        Qs[(d4 * 4 + 0) * QPAD + q] = v.x * 0.125f;
        Qs[(d4 * 4 + 1) * QPAD + q] = v.y * 0.125f;
        Qs[(d4 * 4 + 2) * QPAD + q] = v.z * 0.125f;
        Qs[(d4 * 4 + 3) * QPAD + q] = v.w * 0.125f;
    }

    float o[8][4];
#pragma unroll
    for (int i = 0; i < 8; i++)
#pragma unroll
        for (int j = 0; j < 4; j++) o[i][j] = 0.f;

    __syncthreads();

    for (int kt = 0; kt < LL / 64; kt++) {
        const int k0 = kt * 64;
        const float* Kg = g_K + ((size_t)bh * LL + k0) * DH;
        const float* Vg = g_V + ((size_t)bh * LL + k0) * DH;
        // K transposed -> Ks[d][k'] ; V direct -> Vs[k][d'] (both swizzled)
#pragma unroll
        for (int r = 0; r < 4; r++) {
            int i = tid + r * 256;           // 0..1023 float4s
            int kq = i >> 4, d4 = i & 15;
            float4 v = *(const float4*)&Kg[kq * DH + d4 * 4];
            const int kgr = ((kq >> 2) + d4) & 15;   // rotate by d>>2 (= d4)
            const int kin = kq & 3;
            Ks[(d4 * 4 + 0) * KPAD + kgr * 4 + kin] = v.x;
            Ks[(d4 * 4 + 1) * KPAD + kgr * 4 + kin] = v.y;
            Ks[(d4 * 4 + 2) * KPAD + kgr * 4 + kin] = v.z;
            Ks[(d4 * 4 + 3) * KPAD + kgr * 4 + kin] = v.w;
            float4 w = *(const float4*)&Vg[kq * DH + d4 * 4];
            const int vgr = (d4 + (kq >> 2)) & 15;   // rotate by k>>2
            *(float4*)&Vs[kq * KPAD + vgr * 4] = w;
        }
        if (tid < 64) maskf[tid] = (mask[b * LL + k0 + tid] != 0) ? 0.f : -1e30f;
        __syncthreads();

        // ---- S = Q K^T : thread (ty,tx) -> q rows ty*8..+7, k cols tx*4..+3
        float s[8][4];
#pragma unroll
        for (int i = 0; i < 8; i++)
#pragma unroll
            for (int j = 0; j < 4; j++) s[i][j] = 0.f;
#pragma unroll
        for (int kk = 0; kk < 64; kk++) {
            float4 a0 = *(const float4*)&Qs[kk * QPAD + ty * 8];
            float4 a1 = *(const float4*)&Qs[kk * QPAD + ty * 8 + 4];
            float4 bv = *(const float4*)&Ks[kk * KPAD +
                (((tx + (kk >> 2)) & 15) * 4)];
            float a[8] = {a0.x, a0.y, a0.z, a0.w, a1.x, a1.y, a1.z, a1.w};
            float bb[4] = {bv.x, bv.y, bv.z, bv.w};
#pragma unroll
            for (int i = 0; i < 8; i++)
#pragma unroll
                for (int j = 0; j < 4; j++) s[i][j] += a[i] * bb[j];
        }
        // store S transposed: Ss[k][q], q-granule (2ty+e) rotated by row>>2=tx
#pragma unroll
        for (int j = 0; j < 4; j++) {
            float* base = &Ss[(tx * 4 + j) * QPAD];
            *(float4*)&base[(((2 * ty + 0) + tx) & 31) * 4] =
                make_float4(s[0][j], s[1][j], s[2][j], s[3][j]);
            *(float4*)&base[(((2 * ty + 1) + tx) & 31) * 4] =
                make_float4(s[4][j], s[5][j], s[6][j], s[7][j]);
        }
        __syncthreads();

        // ---- streaming softmax: 2 threads per q row, 32 k each ----
        {
            const int r = tid >> 1, c = tid & 1;
            const int qg = q0 + r;
            const int rg = r >> 2, rin = r & 3;
            float vals[32];
            float mx = -1e30f;
#pragma unroll
            for (int u = 0; u < 32; u++) {
                const int kk = c * 32 + u;
                const int kg = k0 + kk;
                int rel = kg - qg;
                rel = rel < -MD ? -MD : (rel > MD ? MD : rel);
                float v = Ss[kk * QPAD + ((rg + (kk >> 2)) & 31) * 4 + rin]
                          + bias_s[rel + MD] + maskf[kk];
                vals[u] = v;
                mx = fmaxf(mx, v);
            }
            mx = fmaxf(mx, __shfl_xor_sync(0xffffffffu, mx, 1));
            const float mold = row_m[r];
            const float mnew = fmaxf(mold, mx);
            float sum = 0.f;
#pragma unroll
            for (int u = 0; u < 32; u++) {
                const int kk = c * 32 + u;
                float e = __expf(vals[u] - mnew);
                Ss[kk * QPAD + ((rg + (kk >> 2)) & 31) * 4 + rin] = e;
                sum += e;
            }
            sum += __shfl_xor_sync(0xffffffffu, sum, 1);
            if (c == 0) {
                float f = __expf(mold - mnew);
                row_f[r] = f;
                row_m[r] = mnew;
                row_l[r] = row_l[r] * f + sum;
            }
        }
        __syncthreads();

        // ---- rescale O, then O += P V (swizzled reads) ----
#pragma unroll
        for (int i = 0; i < 8; i++) {
            const float f = row_f[ty * 8 + i];
#pragma unroll
            for (int j = 0; j < 4; j++) o[i][j] *= f;
        }
#pragma unroll
        for (int kk = 0; kk < 64; kk++) {
            float4 p0 = *(const float4*)&Ss[kk * QPAD +
                (((2 * ty + 0) + (kk >> 2)) & 31) * 4];
            float4 p1 = *(const float4*)&Ss[kk * QPAD +
                (((2 * ty + 1) + (kk >> 2)) & 31) * 4];
            float4 vv = *(const float4*)&Vs[kk * KPAD +
                (((tx + (kk >> 2)) & 15) * 4)];
            float p[8] = {p0.x, p0.y, p0.z, p0.w, p1.x, p1.y, p1.z, p1.w};
#pragma unroll
            for (int i = 0; i < 8; i++) {
                o[i][0] += p[i] * vv.x;
                o[i][1] += p[i] * vv.y;
                o[i][2] += p[i] * vv.z;
                o[i][3] += p[i] * vv.w;
            }
        }
        __syncthreads();   // before next tile overwrites Ks/Vs/Ss
    }

    // epilogue: normalize, write [b, l, h*64+d]
#pragma unroll
    for (int i = 0; i < 8; i++) {
        const int q = ty * 8 + i;
        const float inv = 1.f / row_l[q];
        const int qg = q0 + q;
        *(float4*)&g_AO[((size_t)b * LL + qg) * DM + h * DH + tx * 4] =
            make_float4(o[i][0] * inv, o[i][1] * inv,
                        o[i][2] * inv, o[i][3] * inv);
    }
}

// ---------------------------------------------------------------------------
// GEMM 2 (UNCHANGED from round-2 passing kernel): out = AO @ Wo + bo.
// ---------------------------------------------------------------------------
__global__ __launch_bounds__(256) void out_gemm(
    const float* __restrict__ W, const float* __restrict__ bias,
    float* __restrict__ out) {
    __shared__ float As[16][132];
    __shared__ float Bs[16][128];

    const int tid = threadIdx.x;
    const int tx = tid & 15, ty = tid >> 4;
    const int m0 = blockIdx.y * 128, n0 = blockIdx.x * 128;
    const float* A = g_AO;

    float acc[8][8];
#pragma unroll
    for (int i = 0; i < 8; i++)
#pragma unroll
        for (int j = 0; j < 8; j++) acc[i][j] = 0.f;

    for (int k0 = 0; k0 < 1024; k0 += 16) {
#pragma unroll
        for (int r = 0; r < 2; r++) {
            int i = tid + r * 256;
            int row = i >> 2, c4 = i & 3;
            float4 v = *(const float4*)&A[(size_t)(m0 + row) * 1024 + k0 + c4 * 4];
            As[c4 * 4 + 0][row] = v.x;
            As[c4 * 4 + 1][row] = v.y;
            As[c4 * 4 + 2][row] = v.z;
            As[c4 * 4 + 3][row] = v.w;
        }
#pragma unroll
        for (int r = 0; r < 2; r++) {
            int i = tid + r * 256;
            int row = i >> 5, c4 = i & 31;
            float4 v = *(const float4*)&W[(size_t)(k0 + row) * 1024 + n0 + c4 * 4];
            *(float4*)&Bs[row][c4 * 4] = v;
        }
        __syncthreads();
#pragma unroll
        for (int kk = 0; kk < 16; kk++) {
            float4 a0 = *(const float4*)&As[kk][ty * 4];
            float4 a1 = *(const float4*)&As[kk][64 + ty * 4];
            float4 b0 = *(const float4*)&Bs[kk][tx * 4];
            float4 b1 = *(const float4*)&Bs[kk][64 + tx * 4];
            float a[8] = {a0.x, a0.y, a0.z, a0.w, a1.x, a1.y, a1.z, a1.w};
            float b[8] = {b0.x, b0.y, b0.z, b0.w, b1.x, b1.y, b1.z, b1.w};
#pragma unroll
            for (int i = 0; i < 8; i++)
#pragma unroll
                for (int j = 0; j < 8; j++) acc[i][j] += a[i] * b[j];
        }
        __syncthreads();
    }

#pragma unroll
    for (int i = 0; i < 8; i++) {
        int m = m0 + ((i < 4) ? (ty * 4 + i) : (64 + ty * 4 + i - 4));
#pragma unroll
        for (int jh = 0; jh < 2; jh++) {
            int n = n0 + jh * 64 + tx * 4;
            float4 v;
            v.x = acc[i][jh * 4 + 0] + bias[n + 0];
            v.y = acc[i][jh * 4 + 1] + bias[n + 1];
            v.z = acc[i][jh * 4 + 2] + bias[n + 2];
            v.w = acc[i][jh * 4 + 3] + bias[n + 3];
            *(float4*)&out[(size_t)m * 1024 + n] = v;
        }
    }
}

// ---------------------------------------------------------------------------
extern "C" void kernel_launch(void* const* d_in, const int* in_sizes, int n_in,
                              void* d_out, int out_size) {
    const float* x    = (const float*)d_in[0];
    const int* mask   = (const int*)d_in[1];      // bool -> int32 in harness
    const float* Wqkv = (const float*)d_in[2];
    const float* bqkv = (const float*)d_in[3];
    const float* Wo   = (const float*)d_in[4];
    const float* bo   = (const float*)d_in[5];
    const float* rb   = (const float*)d_in[6];
    float* out        = (float*)d_out;

    qkv_gemm<<<dim3(3072 / 128, 8192 / 128), 256>>>(x, Wqkv, bqkv);

    const int smem_bytes = ATTN_SMEM_FLOATS * (int)sizeof(float);
    cudaFuncSetAttribute(attn_kernel,
                         cudaFuncAttributeMaxDynamicSharedMemorySize, smem_bytes);
    attn_kernel<<<dim3(LL / QT, BB * NH), 256, smem_bytes>>>(mask, rb);

    out_gemm<<<dim3(1024 / 128, 8192 / 128), 256>>>(Wo, bo, out);
}

// round 12
// speedup vs baseline: 1.0322x; 1.0232x over previous
#include <cuda_runtime.h>
#include <cuda_bf16.h>

// Problem constants
#define BB 4
#define LL 2048
#define DM 1024
#define NH 16
#define DH 64
#define MD 128          // MAX_DIST
#define NBIAS 257       // 2*MD+1

// Scratch (device globals: allocation-free rule)
__device__ float g_Q[BB * NH * LL * DH];   // [b,h,l,d]
__device__ float g_K[BB * NH * LL * DH];
__device__ float g_V[BB * NH * LL * DH];
__device__ float g_AO[BB * LL * DM];       // attention out, [b,l,h*64+d]

// ---------------------------------------------------------------------------
// GEMM 1 (UNCHANGED from round-2 passing kernel):
// qkv = x @ Wqkv + bqkv, scattered into g_Q/g_K/g_V head layout.
// ---------------------------------------------------------------------------
__global__ __launch_bounds__(256) void qkv_gemm(
    const float* __restrict__ X, const float* __restrict__ W,
    const float* __restrict__ bias) {
    __shared__ float As[16][132];
    __shared__ float Bs[16][128];

    const int tid = threadIdx.x;
    const int tx = tid & 15, ty = tid >> 4;
    const int m0 = blockIdx.y * 128, n0 = blockIdx.x * 128;

    float acc[8][8];
#pragma unroll
    for (int i = 0; i < 8; i++)
#pragma unroll
        for (int j = 0; j < 8; j++) acc[i][j] = 0.f;

    for (int k0 = 0; k0 < 1024; k0 += 16) {
#pragma unroll
        for (int r = 0; r < 2; r++) {
            int i = tid + r * 256;
            int row = i >> 2, c4 = i & 3;
            float4 v = *(const float4*)&X[(size_t)(m0 + row) * 1024 + k0 + c4 * 4];
            As[c4 * 4 + 0][row] = v.x;
            As[c4 * 4 + 1][row] = v.y;
            As[c4 * 4 + 2][row] = v.z;
            As[c4 * 4 + 3][row] = v.w;
        }
#pragma unroll
        for (int r = 0; r < 2; r++) {
            int i = tid + r * 256;
            int row = i >> 5, c4 = i & 31;
            float4 v = *(const float4*)&W[(size_t)(k0 + row) * 3072 + n0 + c4 * 4];
            *(float4*)&Bs[row][c4 * 4] = v;
        }
        __syncthreads();

#pragma unroll
        for (int kk = 0; kk < 16; kk++) {
            float4 a0 = *(const float4*)&As[kk][ty * 4];
            float4 a1 = *(const float4*)&As[kk][64 + ty * 4];
            float4 b0 = *(const float4*)&Bs[kk][tx * 4];
            float4 b1 = *(const float4*)&Bs[kk][64 + tx * 4];
            float a[8] = {a0.x, a0.y, a0.z, a0.w, a1.x, a1.y, a1.z, a1.w};
            float b[8] = {b0.x, b0.y, b0.z, b0.w, b1.x, b1.y, b1.z, b1.w};
#pragma unroll
            for (int i = 0; i < 8; i++)
#pragma unroll
                for (int j = 0; j < 8; j++) acc[i][j] += a[i] * b[j];
        }
        __syncthreads();
    }

#pragma unroll
    for (int i = 0; i < 8; i++) {
        int m = m0 + ((i < 4) ? (ty * 4 + i) : (64 + ty * 4 + i - 4));
        int b = m >> 11, l = m & 2047;
#pragma unroll
        for (int jh = 0; jh < 2; jh++) {
            int n = n0 + jh * 64 + tx * 4;
            float4 v;
            v.x = acc[i][jh * 4 + 0] + bias[n + 0];
            v.y = acc[i][jh * 4 + 1] + bias[n + 1];
            v.z = acc[i][jh * 4 + 2] + bias[n + 2];
            v.w = acc[i][jh * 4 + 3] + bias[n + 3];
            int which = n >> 10;
            int nn = n & 1023;
            int h = nn >> 6, d = nn & 63;
            float* dst = (which == 0) ? g_Q : (which == 1) ? g_K : g_V;
            *(float4*)&dst[((size_t)(b * NH + h) * LL + l) * DH + d] = v;
        }
    }
}

// ---------------------------------------------------------------------------
// Attention v5 = R8 structure + software-pipelined K/V loads (LDG -> regs for
// tile kt+1 issued right after the staging sync; latency hidden by compute).
// Only safe instructions: LDG/STS/LDS/FFMA/MUFU/SHFL/BAR.
// ---------------------------------------------------------------------------
#define QT 128              // q rows per block
#define QPAD 132            // padded q stride
#define KPAD 68             // padded k/d stride
#define ATTN_SMEM_FLOATS (64 * QPAD + 64 * KPAD + 64 * KPAD + 64 * QPAD + \
                          NBIAS + 3 * QT + 64)

__global__ __launch_bounds__(256) void attn_kernel(
    const int* __restrict__ mask, const float* __restrict__ rel_bias) {
    extern __shared__ float sm[];
    float* Qs = sm;                          // [d=64][q=128] (+pad)
    float* Ks = Qs + 64 * QPAD;              // [d=64][k=64]  (+pad)
    float* Vs = Ks + 64 * KPAD;              // [k=64][d=64]  (+pad)
    float* Ss = Vs + 64 * KPAD;              // [k=64][q=128] (+pad)  S / P
    float* bias_s = Ss + 64 * QPAD;          // 257
    float* row_m = bias_s + NBIAS;           // 128
    float* row_l = row_m + QT;               // 128
    float* row_f = row_l + QT;               // 128
    float* maskf = row_f + QT;               // 64

    const int tid = threadIdx.x;
    const int tx = tid & 15, ty = tid >> 4;  // tx: k/d quad, ty: q octet
    const int bh = blockIdx.y;
    const int b = bh / NH, h = bh % NH;
    const int q0 = blockIdx.x * QT;

    for (int i = tid; i < NBIAS; i += 256) bias_s[i] = rel_bias[h * NBIAS + i];
    if (tid < QT) { row_m[tid] = -1e30f; row_l[tid] = 0.f; }

    // Q tile transposed -> Qs[d][q], scale folded
    const float* Qg = g_Q + ((size_t)bh * LL + q0) * DH;
#pragma unroll
    for (int r = 0; r < 8; r++) {
        int i = tid + r * 256;               // 0..2047 float4s
        int q = i >> 4, d4 = i & 15;
        float4 v = *(const float4*)&Qg[q * DH + d4 * 4];
        Qs[(d4 * 4 + 0) * QPAD + q] = v.x * 0.125f;
        Qs[(d4 * 4 + 1) * QPAD + q] = v.y * 0.125f;
        Qs[(d4 * 4 + 2) * QPAD + q] = v.z * 0.125f;
        Qs[(d4 * 4 + 3) * QPAD + q] = v.w * 0.125f;
    }

    float o[8][4];
#pragma unroll
    for (int i = 0; i < 8; i++)
#pragma unroll
        for (int j = 0; j < 4; j++) o[i][j] = 0.f;

    // per-thread staging coordinates (same for every tile)
    const int skq = tid >> 4;                // 0..15 : k row (pairs with +16 step? no: i>>4 for r loop)
    // staging uses i = tid + r*256 -> kq = i>>4, d4 = i&15.  d4 is constant
    // per thread (tid&15), kq = (tid>>4) + r*16.
    const int sd4 = tid & 15;

    // prologue: prefetch tile 0 K/V into registers
    float4 kreg[4], vreg[4];
    int mreg = 0;
    {
        const float* Kg = g_K + ((size_t)bh * LL + 0) * DH;
        const float* Vg = g_V + ((size_t)bh * LL + 0) * DH;
#pragma unroll
        for (int r = 0; r < 4; r++) {
            int kq = skq + r * 16;
            kreg[r] = *(const float4*)&Kg[kq * DH + sd4 * 4];
            vreg[r] = *(const float4*)&Vg[kq * DH + sd4 * 4];
        }
        if (tid < 64) mreg = mask[b * LL + tid];
    }

    __syncthreads();

    for (int kt = 0; kt < LL / 64; kt++) {
        const int k0 = kt * 64;

        // ---- stage prefetched K/V regs into smem ----
#pragma unroll
        for (int r = 0; r < 4; r++) {
            int kq = skq + r * 16;
            Ks[(sd4 * 4 + 0) * KPAD + kq] = kreg[r].x;
            Ks[(sd4 * 4 + 1) * KPAD + kq] = kreg[r].y;
            Ks[(sd4 * 4 + 2) * KPAD + kq] = kreg[r].z;
            Ks[(sd4 * 4 + 3) * KPAD + kq] = kreg[r].w;
            *(float4*)&Vs[kq * KPAD + sd4 * 4] = vreg[r];
        }
        if (tid < 64) maskf[tid] = (mreg != 0) ? 0.f : -1e30f;
        __syncthreads();

        // ---- issue prefetch for tile kt+1 (latency hidden by compute) ----
        if (kt + 1 < LL / 64) {
            const int kn = k0 + 64;
            const float* Kg = g_K + ((size_t)bh * LL + kn) * DH;
            const float* Vg = g_V + ((size_t)bh * LL + kn) * DH;
#pragma unroll
            for (int r = 0; r < 4; r++) {
                int kq = skq + r * 16;
                kreg[r] = *(const float4*)&Kg[kq * DH + sd4 * 4];
                vreg[r] = *(const float4*)&Vg[kq * DH + sd4 * 4];
            }
            if (tid < 64) mreg = mask[b * LL + kn + tid];
        }

        // ---- S = Q K^T : thread (ty,tx) -> q rows ty*8..+7, k cols tx*4..+3
        float s[8][4];
#pragma unroll
        for (int i = 0; i < 8; i++)
#pragma unroll
            for (int j = 0; j < 4; j++) s[i][j] = 0.f;
#pragma unroll
        for (int kk = 0; kk < 64; kk++) {
            float4 a0 = *(const float4*)&Qs[kk * QPAD + ty * 8];
            float4 a1 = *(const float4*)&Qs[kk * QPAD + ty * 8 + 4];
            float4 bv = *(const float4*)&Ks[kk * KPAD + tx * 4];
            float a[8] = {a0.x, a0.y, a0.z, a0.w, a1.x, a1.y, a1.z, a1.w};
            float bb[4] = {bv.x, bv.y, bv.z, bv.w};
#pragma unroll
            for (int i = 0; i < 8; i++)
#pragma unroll
                for (int j = 0; j < 4; j++) s[i][j] += a[i] * bb[j];
        }
        // store S transposed: Ss[k][q]
#pragma unroll
        for (int j = 0; j < 4; j++) {
            float* dst = &Ss[(tx * 4 + j) * QPAD + ty * 8];
            *(float4*)&dst[0] = make_float4(s[0][j], s[1][j], s[2][j], s[3][j]);
            *(float4*)&dst[4] = make_float4(s[4][j], s[5][j], s[6][j], s[7][j]);
        }
        __syncthreads();

        // ---- streaming softmax: 2 threads per q row, 32 k each ----
        {
            const int r = tid >> 1, c = tid & 1;
            const int qg = q0 + r;
            float vals[32];
            float mx = -1e30f;
#pragma unroll
            for (int u = 0; u < 32; u++) {
                const int kk = c * 32 + u;
                const int kg = k0 + kk;
                int rel = kg - qg;
                rel = rel < -MD ? -MD : (rel > MD ? MD : rel);
                float v = Ss[kk * QPAD + r] + bias_s[rel + MD] + maskf[kk];
                vals[u] = v;
                mx = fmaxf(mx, v);
            }
            mx = fmaxf(mx, __shfl_xor_sync(0xffffffffu, mx, 1));
            const float mold = row_m[r];
            const float mnew = fmaxf(mold, mx);
            float sum = 0.f;
#pragma unroll
            for (int u = 0; u < 32; u++) {
                float e = __expf(vals[u] - mnew);
                Ss[(c * 32 + u) * QPAD + r] = e;
                sum += e;
            }
            sum += __shfl_xor_sync(0xffffffffu, sum, 1);
            if (c == 0) {
                float f = __expf(mold - mnew);
                row_f[r] = f;
                row_m[r] = mnew;
                row_l[r] = row_l[r] * f + sum;
            }
        }
        __syncthreads();

        // ---- rescale O, then O += P V : P = Ss[k][q], V = Vs[k][d] ----
#pragma unroll
        for (int i = 0; i < 8; i++) {
            const float f = row_f[ty * 8 + i];
#pragma unroll
            for (int j = 0; j < 4; j++) o[i][j] *= f;
        }
#pragma unroll
        for (int kk = 0; kk < 64; kk++) {
            float4 p0 = *(const float4*)&Ss[kk * QPAD + ty * 8];
            float4 p1 = *(const float4*)&Ss[kk * QPAD + ty * 8 + 4];
            float4 vv = *(const float4*)&Vs[kk * KPAD + tx * 4];
            float p[8] = {p0.x, p0.y, p0.z, p0.w, p1.x, p1.y, p1.z, p1.w};
#pragma unroll
            for (int i = 0; i < 8; i++) {
                o[i][0] += p[i] * vv.x;
                o[i][1] += p[i] * vv.y;
                o[i][2] += p[i] * vv.z;
                o[i][3] += p[i] * vv.w;
            }
        }
        __syncthreads();   // before next tile's staging overwrites Ks/Vs/Ss
    }

    // epilogue: normalize, write [b, l, h*64+d]
#pragma unroll
    for (int i = 0; i < 8; i++) {
        const int q = ty * 8 + i;
        const float inv = 1.f / row_l[q];
        const int qg = q0 + q;
        *(float4*)&g_AO[((size_t)b * LL + qg) * DM + h * DH + tx * 4] =
            make_float4(o[i][0] * inv, o[i][1] * inv,
                        o[i][2] * inv, o[i][3] * inv);
    }
}

// ---------------------------------------------------------------------------
// GEMM 2 (UNCHANGED from round-2 passing kernel): out = AO @ Wo + bo.
// ---------------------------------------------------------------------------
__global__ __launch_bounds__(256) void out_gemm(
    const float* __restrict__ W, const float* __restrict__ bias,
    float* __restrict__ out) {
    __shared__ float As[16][132];
    __shared__ float Bs[16][128];

    const int tid = threadIdx.x;
    const int tx = tid & 15, ty = tid >> 4;
    const int m0 = blockIdx.y * 128, n0 = blockIdx.x * 128;
    const float* A = g_AO;

    float acc[8][8];
#pragma unroll
    for (int i = 0; i < 8; i++)
#pragma unroll
        for (int j = 0; j < 8; j++) acc[i][j] = 0.f;

    for (int k0 = 0; k0 < 1024; k0 += 16) {
#pragma unroll
        for (int r = 0; r < 2; r++) {
            int i = tid + r * 256;
            int row = i >> 2, c4 = i & 3;
            float4 v = *(const float4*)&A[(size_t)(m0 + row) * 1024 + k0 + c4 * 4];
            As[c4 * 4 + 0][row] = v.x;
            As[c4 * 4 + 1][row] = v.y;
            As[c4 * 4 + 2][row] = v.z;
            As[c4 * 4 + 3][row] = v.w;
        }
#pragma unroll
        for (int r = 0; r < 2; r++) {
            int i = tid + r * 256;
            int row = i >> 5, c4 = i & 31;
            float4 v = *(const float4*)&W[(size_t)(k0 + row) * 1024 + n0 + c4 * 4];
            *(float4*)&Bs[row][c4 * 4] = v;
        }
        __syncthreads();
#pragma unroll
        for (int kk = 0; kk < 16; kk++) {
            float4 a0 = *(const float4*)&As[kk][ty * 4];
            float4 a1 = *(const float4*)&As[kk][64 + ty * 4];
            float4 b0 = *(const float4*)&Bs[kk][tx * 4];
            float4 b1 = *(const float4*)&Bs[kk][64 + tx * 4];
            float a[8] = {a0.x, a0.y, a0.z, a0.w, a1.x, a1.y, a1.z, a1.w};
            float b[8] = {b0.x, b0.y, b0.z, b0.w, b1.x, b1.y, b1.z, b1.w};
#pragma unroll
            for (int i = 0; i < 8; i++)
#pragma unroll
                for (int j = 0; j < 8; j++) acc[i][j] += a[i] * b[j];
        }
        __syncthreads();
    }

#pragma unroll
    for (int i = 0; i < 8; i++) {
        int m = m0 + ((i < 4) ? (ty * 4 + i) : (64 + ty * 4 + i - 4));
#pragma unroll
        for (int jh = 0; jh < 2; jh++) {
            int n = n0 + jh * 64 + tx * 4;
            float4 v;
            v.x = acc[i][jh * 4 + 0] + bias[n + 0];
            v.y = acc[i][jh * 4 + 1] + bias[n + 1];
            v.z = acc[i][jh * 4 + 2] + bias[n + 2];
            v.w = acc[i][jh * 4 + 3] + bias[n + 3];
            *(float4*)&out[(size_t)m * 1024 + n] = v;
        }
    }
}

// ---------------------------------------------------------------------------
extern "C" void kernel_launch(void* const* d_in, const int* in_sizes, int n_in,
                              void* d_out, int out_size) {
    const float* x    = (const float*)d_in[0];
    const int* mask   = (const int*)d_in[1];      // bool -> int32 in harness
    const float* Wqkv = (const float*)d_in[2];
    const float* bqkv = (const float*)d_in[3];
    const float* Wo   = (const float*)d_in[4];
    const float* bo   = (const float*)d_in[5];
    const float* rb   = (const float*)d_in[6];
    float* out        = (float*)d_out;

    qkv_gemm<<<dim3(3072 / 128, 8192 / 128), 256>>>(x, Wqkv, bqkv);

    const int smem_bytes = ATTN_SMEM_FLOATS * (int)sizeof(float);
    cudaFuncSetAttribute(attn_kernel,
                         cudaFuncAttributeMaxDynamicSharedMemorySize, smem_bytes);
    attn_kernel<<<dim3(LL / QT, BB * NH), 256, smem_bytes>>>(mask, rb);

    out_gemm<<<dim3(1024 / 128, 8192 / 128), 256>>>(Wo, bo, out);
}

// round 14
// speedup vs baseline: 1.0567x; 1.0238x over previous
#include <cuda_runtime.h>
#include <cuda_bf16.h>

// Problem constants
#define BB 4
#define LL 2048
#define DM 1024
#define NH 16
#define DH 64
#define MD 128          // MAX_DIST
#define NBIAS 257       // 2*MD+1

// Scratch (device globals: allocation-free rule)
__device__ float g_Q[BB * NH * LL * DH];   // [b,h,l,d]
__device__ float g_K[BB * NH * LL * DH];
__device__ float g_V[BB * NH * LL * DH];
__device__ float g_AO[BB * LL * DM];       // attention out, [b,l,h*64+d]

// ---------------------------------------------------------------------------
// GEMM 1 v3: qkv = x @ Wqkv + bqkv. Same 128x128 tile / 8x8 micro-kernel as
// R2, but k-step 32: half the barriers, deeper LDG batching per staging wait.
// ---------------------------------------------------------------------------
__global__ __launch_bounds__(256) void qkv_gemm(
    const float* __restrict__ X, const float* __restrict__ W,
    const float* __restrict__ bias) {
    __shared__ float As[32][132];   // [kk][m] transposed, padded
    __shared__ float Bs[32][128];   // [kk][n]

    const int tid = threadIdx.x;
    const int tx = tid & 15, ty = tid >> 4;
    const int m0 = blockIdx.y * 128, n0 = blockIdx.x * 128;

    float acc[8][8];
#pragma unroll
    for (int i = 0; i < 8; i++)
#pragma unroll
        for (int j = 0; j < 8; j++) acc[i][j] = 0.f;

    for (int k0 = 0; k0 < 1024; k0 += 32) {
        // A tile: 128 rows x 32 k -> As[kk][row]; 1024 float4, 4 per thread
#pragma unroll
        for (int r = 0; r < 4; r++) {
            int i = tid + r * 256;
            int row = i >> 3, c4 = i & 7;
            float4 v = *(const float4*)&X[(size_t)(m0 + row) * 1024 + k0 + c4 * 4];
            As[c4 * 4 + 0][row] = v.x;
            As[c4 * 4 + 1][row] = v.y;
            As[c4 * 4 + 2][row] = v.z;
            As[c4 * 4 + 3][row] = v.w;
        }
        // B tile: 32 k x 128 n; 1024 float4, 4 per thread
#pragma unroll
        for (int r = 0; r < 4; r++) {
            int i = tid + r * 256;
            int row = i >> 5, c4 = i & 31;
            float4 v = *(const float4*)&W[(size_t)(k0 + row) * 3072 + n0 + c4 * 4];
            *(float4*)&Bs[row][c4 * 4] = v;
        }
        __syncthreads();

#pragma unroll
        for (int kk = 0; kk < 32; kk++) {
            float4 a0 = *(const float4*)&As[kk][ty * 4];
            float4 a1 = *(const float4*)&As[kk][64 + ty * 4];
            float4 b0 = *(const float4*)&Bs[kk][tx * 4];
            float4 b1 = *(const float4*)&Bs[kk][64 + tx * 4];
            float a[8] = {a0.x, a0.y, a0.z, a0.w, a1.x, a1.y, a1.z, a1.w};
            float b[8] = {b0.x, b0.y, b0.z, b0.w, b1.x, b1.y, b1.z, b1.w};
#pragma unroll
            for (int i = 0; i < 8; i++)
#pragma unroll
                for (int j = 0; j < 8; j++) acc[i][j] += a[i] * b[j];
        }
        __syncthreads();
    }

    // Epilogue: add bias, scatter into Q/K/V head layout
#pragma unroll
    for (int i = 0; i < 8; i++) {
        int m = m0 + ((i < 4) ? (ty * 4 + i) : (64 + ty * 4 + i - 4));
        int b = m >> 11, l = m & 2047;
#pragma unroll
        for (int jh = 0; jh < 2; jh++) {
            int n = n0 + jh * 64 + tx * 4;
            float4 v;
            v.x = acc[i][jh * 4 + 0] + bias[n + 0];
            v.y = acc[i][jh * 4 + 1] + bias[n + 1];
            v.z = acc[i][jh * 4 + 2] + bias[n + 2];
            v.w = acc[i][jh * 4 + 3] + bias[n + 3];
            int which = n >> 10;
            int nn = n & 1023;
            int h = nn >> 6, d = nn & 63;
            float* dst = (which == 0) ? g_Q : (which == 1) ? g_K : g_V;
            *(float4*)&dst[((size_t)(b * NH + h) * LL + l) * DH + d] = v;
        }
    }
}

// ---------------------------------------------------------------------------
// Attention (EXACT R8, the 3203-us config — frozen; 2 blocks/SM invariant).
// ---------------------------------------------------------------------------
#define QT 128              // q rows per block
#define QPAD 132            // padded q stride
#define KPAD 68             // padded k/d stride
#define ATTN_SMEM_FLOATS (64 * QPAD + 64 * KPAD + 64 * KPAD + 64 * QPAD + \
                          NBIAS + 3 * QT + 64)

__global__ __launch_bounds__(256) void attn_kernel(
    const int* __restrict__ mask, const float* __restrict__ rel_bias) {
    extern __shared__ float sm[];
    float* Qs = sm;                          // [d=64][q=128] (+pad)
    float* Ks = Qs + 64 * QPAD;              // [d=64][k=64]  (+pad)
    float* Vs = Ks + 64 * KPAD;              // [k=64][d=64]  (+pad)
    float* Ss = Vs + 64 * KPAD;              // [k=64][q=128] (+pad)  S / P
    float* bias_s = Ss + 64 * QPAD;          // 257
    float* row_m = bias_s + NBIAS;           // 128
    float* row_l = row_m + QT;               // 128
    float* row_f = row_l + QT;               // 128
    float* maskf = row_f + QT;               // 64

    const int tid = threadIdx.x;
    const int tx = tid & 15, ty = tid >> 4;  // tx: k/d quad, ty: q octet
    const int bh = blockIdx.y;
    const int b = bh / NH, h = bh % NH;
    const int q0 = blockIdx.x * QT;

    for (int i = tid; i < NBIAS; i += 256) bias_s[i] = rel_bias[h * NBIAS + i];
    if (tid < QT) { row_m[tid] = -1e30f; row_l[tid] = 0.f; }

    // Q tile transposed -> Qs[d][q], scale folded
    const float* Qg = g_Q + ((size_t)bh * LL + q0) * DH;
#pragma unroll
    for (int r = 0; r < 8; r++) {
        int i = tid + r * 256;               // 0..2047 float4s
        int q = i >> 4, d4 = i & 15;
        float4 v = *(const float4*)&Qg[q * DH + d4 * 4];
        Qs[(d4 * 4 + 0) * QPAD + q] = v.x * 0.125f;
        Qs[(d4 * 4 + 1) * QPAD + q] = v.y * 0.125f;
        Qs[(d4 * 4 + 2) * QPAD + q] = v.z * 0.125f;
        Qs[(d4 * 4 + 3) * QPAD + q] = v.w * 0.125f;
    }

    float o[8][4];
#pragma unroll
    for (int i = 0; i < 8; i++)
#pragma unroll
        for (int j = 0; j < 4; j++) o[i][j] = 0.f;

    __syncthreads();

    for (int kt = 0; kt < LL / 64; kt++) {
        const int k0 = kt * 64;
        const float* Kg = g_K + ((size_t)bh * LL + k0) * DH;
        const float* Vg = g_V + ((size_t)bh * LL + k0) * DH;
        // K transposed -> Ks[d][k]; V direct -> Vs[k][d]
#pragma unroll
        for (int r = 0; r < 4; r++) {
            int i = tid + r * 256;           // 0..1023 float4s
            int kq = i >> 4, d4 = i & 15;
            float4 v = *(const float4*)&Kg[kq * DH + d4 * 4];
            Ks[(d4 * 4 + 0) * KPAD + kq] = v.x;
            Ks[(d4 * 4 + 1) * KPAD + kq] = v.y;
            Ks[(d4 * 4 + 2) * KPAD + kq] = v.z;
            Ks[(d4 * 4 + 3) * KPAD + kq] = v.w;
            float4 w = *(const float4*)&Vg[kq * DH + d4 * 4];
            *(float4*)&Vs[kq * KPAD + d4 * 4] = w;
        }
        if (tid < 64) maskf[tid] = (mask[b * LL + k0 + tid] != 0) ? 0.f : -1e30f;
        __syncthreads();

        // ---- S = Q K^T : thread (ty,tx) -> q rows ty*8..+7, k cols tx*4..+3
        float s[8][4];
#pragma unroll
        for (int i = 0; i < 8; i++)
#pragma unroll
            for (int j = 0; j < 4; j++) s[i][j] = 0.f;
#pragma unroll
        for (int kk = 0; kk < 64; kk++) {
            float4 a0 = *(const float4*)&Qs[kk * QPAD + ty * 8];
            float4 a1 = *(const float4*)&Qs[kk * QPAD + ty * 8 + 4];
            float4 bv = *(const float4*)&Ks[kk * KPAD + tx * 4];
            float a[8] = {a0.x, a0.y, a0.z, a0.w, a1.x, a1.y, a1.z, a1.w};
            float bb[4] = {bv.x, bv.y, bv.z, bv.w};
#pragma unroll
            for (int i = 0; i < 8; i++)
#pragma unroll
                for (int j = 0; j < 4; j++) s[i][j] += a[i] * bb[j];
        }
        // store S transposed: Ss[k][q]
#pragma unroll
        for (int j = 0; j < 4; j++) {
            float* dst = &Ss[(tx * 4 + j) * QPAD + ty * 8];
            *(float4*)&dst[0] = make_float4(s[0][j], s[1][j], s[2][j], s[3][j]);
            *(float4*)&dst[4] = make_float4(s[4][j], s[5][j], s[6][j], s[7][j]);
        }
        __syncthreads();

        // ---- streaming softmax: 2 threads per q row, 32 k each ----
        {
            const int r = tid >> 1, c = tid & 1;
            const int qg = q0 + r;
            float vals[32];
            float mx = -1e30f;
#pragma unroll
            for (int u = 0; u < 32; u++) {
                const int kk = c * 32 + u;
                const int kg = k0 + kk;
                int rel = kg - qg;
                rel = rel < -MD ? -MD : (rel > MD ? MD : rel);
                float v = Ss[kk * QPAD + r] + bias_s[rel + MD] + maskf[kk];
                vals[u] = v;
                mx = fmaxf(mx, v);
            }
            mx = fmaxf(mx, __shfl_xor_sync(0xffffffffu, mx, 1));
            const float mold = row_m[r];
            const float mnew = fmaxf(mold, mx);
            float sum = 0.f;
#pragma unroll
            for (int u = 0; u < 32; u++) {
                float e = __expf(vals[u] - mnew);
                Ss[(c * 32 + u) * QPAD + r] = e;
                sum += e;
            }
            sum += __shfl_xor_sync(0xffffffffu, sum, 1);
            if (c == 0) {
                float f = __expf(mold - mnew);
                row_f[r] = f;
                row_m[r] = mnew;
                row_l[r] = row_l[r] * f + sum;
            }
        }
        __syncthreads();

        // ---- rescale O, then O += P V : P = Ss[k][q], V = Vs[k][d] ----
#pragma unroll
        for (int i = 0; i < 8; i++) {
            const float f = row_f[ty * 8 + i];
#pragma unroll
            for (int j = 0; j < 4; j++) o[i][j] *= f;
        }
#pragma unroll
        for (int kk = 0; kk < 64; kk++) {
            float4 p0 = *(const float4*)&Ss[kk * QPAD + ty * 8];
            float4 p1 = *(const float4*)&Ss[kk * QPAD + ty * 8 + 4];
            float4 vv = *(const float4*)&Vs[kk * KPAD + tx * 4];
            float p[8] = {p0.x, p0.y, p0.z, p0.w, p1.x, p1.y, p1.z, p1.w};
#pragma unroll
            for (int i = 0; i < 8; i++) {
                o[i][0] += p[i] * vv.x;
                o[i][1] += p[i] * vv.y;
                o[i][2] += p[i] * vv.z;
                o[i][3] += p[i] * vv.w;
            }
        }
        __syncthreads();   // before next tile overwrites Ks/Vs/Ss
    }

    // epilogue: normalize, write [b, l, h*64+d]
#pragma unroll
    for (int i = 0; i < 8; i++) {
        const int q = ty * 8 + i;
        const float inv = 1.f / row_l[q];
        const int qg = q0 + q;
        *(float4*)&g_AO[((size_t)b * LL + qg) * DM + h * DH + tx * 4] =
            make_float4(o[i][0] * inv, o[i][1] * inv,
                        o[i][2] * inv, o[i][3] * inv);
    }
}

// ---------------------------------------------------------------------------
// GEMM 2 v3: out = AO @ Wo + bo, k-step 32 (same change as qkv).
// ---------------------------------------------------------------------------
__global__ __launch_bounds__(256) void out_gemm(
    const float* __restrict__ W, const float* __restrict__ bias,
    float* __restrict__ out) {
    __shared__ float As[32][132];
    __shared__ float Bs[32][128];

    const int tid = threadIdx.x;
    const int tx = tid & 15, ty = tid >> 4;
    const int m0 = blockIdx.y * 128, n0 = blockIdx.x * 128;
    const float* A = g_AO;

    float acc[8][8];
#pragma unroll
    for (int i = 0; i < 8; i++)
#pragma unroll
        for (int j = 0; j < 8; j++) acc[i][j] = 0.f;

    for (int k0 = 0; k0 < 1024; k0 += 32) {
#pragma unroll
        for (int r = 0; r < 4; r++) {
            int i = tid + r * 256;
            int row = i >> 3, c4 = i & 7;
            float4 v = *(const float4*)&A[(size_t)(m0 + row) * 1024 + k0 + c4 * 4];
            As[c4 * 4 + 0][row] = v.x;
            As[c4 * 4 + 1][row] = v.y;
            As[c4 * 4 + 2][row] = v.z;
            As[c4 * 4 + 3][row] = v.w;
        }
#pragma unroll
        for (int r = 0; r < 4; r++) {
            int i = tid + r * 256;
            int row = i >> 5, c4 = i & 31;
            float4 v = *(const float4*)&W[(size_t)(k0 + row) * 1024 + n0 + c4 * 4];
            *(float4*)&Bs[row][c4 * 4] = v;
        }
        __syncthreads();
#pragma unroll
        for (int kk = 0; kk < 32; kk++) {
            float4 a0 = *(const float4*)&As[kk][ty * 4];
            float4 a1 = *(const float4*)&As[kk][64 + ty * 4];
            float4 b0 = *(const float4*)&Bs[kk][tx * 4];
            float4 b1 = *(const float4*)&Bs[kk][64 + tx * 4];
            float a[8] = {a0.x, a0.y, a0.z, a0.w, a1.x, a1.y, a1.z, a1.w};
            float b[8] = {b0.x, b0.y, b0.z, b0.w, b1.x, b1.y, b1.z, b1.w};
#pragma unroll
            for (int i = 0; i < 8; i++)
#pragma unroll
                for (int j = 0; j < 8; j++) acc[i][j] += a[i] * b[j];
        }
        __syncthreads();
    }

#pragma unroll
    for (int i = 0; i < 8; i++) {
        int m = m0 + ((i < 4) ? (ty * 4 + i) : (64 + ty * 4 + i - 4));
#pragma unroll
        for (int jh = 0; jh < 2; jh++) {
            int n = n0 + jh * 64 + tx * 4;
            float4 v;
            v.x = acc[i][jh * 4 + 0] + bias[n + 0];
            v.y = acc[i][jh * 4 + 1] + bias[n + 1];
            v.z = acc[i][jh * 4 + 2] + bias[n + 2];
            v.w = acc[i][jh * 4 + 3] + bias[n + 3];
            *(float4*)&out[(size_t)m * 1024 + n] = v;
        }
    }
}

// ---------------------------------------------------------------------------
extern "C" void kernel_launch(void* const* d_in, const int* in_sizes, int n_in,
                              void* d_out, int out_size) {
    const float* x    = (const float*)d_in[0];
    const int* mask   = (const int*)d_in[1];      // bool -> int32 in harness
    const float* Wqkv = (const float*)d_in[2];
    const float* bqkv = (const float*)d_in[3];
    const float* Wo   = (const float*)d_in[4];
    const float* bo   = (const float*)d_in[5];
    const float* rb   = (const float*)d_in[6];
    float* out        = (float*)d_out;

    qkv_gemm<<<dim3(3072 / 128, 8192 / 128), 256>>>(x, Wqkv, bqkv);

    const int smem_bytes = ATTN_SMEM_FLOATS * (int)sizeof(float);
    cudaFuncSetAttribute(attn_kernel,
                         cudaFuncAttributeMaxDynamicSharedMemorySize, smem_bytes);
    attn_kernel<<<dim3(LL / QT, BB * NH), 256, smem_bytes>>>(mask, rb);

    out_gemm<<<dim3(1024 / 128, 8192 / 128), 256>>>(Wo, bo, out);
}

// round 17
// speedup vs baseline: 1.0637x; 1.0066x over previous
#include <cuda_runtime.h>
#include <cuda_bf16.h>

// Problem constants
#define BB 4
#define LL 2048
#define DM 1024
#define NH 16
#define DH 64
#define MD 128          // MAX_DIST
#define NBIAS 257       // 2*MD+1

// Scratch (device globals: allocation-free rule)
__device__ float g_Q[BB * NH * LL * DH];   // [b,h,l,d]
__device__ float g_K[BB * NH * LL * DH];
__device__ float g_V[BB * NH * LL * DH];
__device__ float g_AO[BB * LL * DM];       // attention out, [b,l,h*64+d]

// ---------------------------------------------------------------------------
// GEMM 1 (R2 exact): qkv = x @ Wqkv + bqkv, scattered into Q/K/V head layout.
// 128x128x16 tiles, 256 threads, 8x8 micro-tile. Verified stack-frame-0.
// ---------------------------------------------------------------------------
__global__ __launch_bounds__(256) void qkv_gemm(
    const float* __restrict__ X, const float* __restrict__ W,
    const float* __restrict__ bias) {
    __shared__ float As[16][132];
    __shared__ float Bs[16][128];

    const int tid = threadIdx.x;
    const int tx = tid & 15, ty = tid >> 4;
    const int m0 = blockIdx.y * 128, n0 = blockIdx.x * 128;

    float acc[8][8];
#pragma unroll
    for (int i = 0; i < 8; i++)
#pragma unroll
        for (int j = 0; j < 8; j++) acc[i][j] = 0.f;

    for (int k0 = 0; k0 < 1024; k0 += 16) {
#pragma unroll
        for (int r = 0; r < 2; r++) {
            int i = tid + r * 256;
            int row = i >> 2, c4 = i & 3;
            float4 v = *(const float4*)&X[(size_t)(m0 + row) * 1024 + k0 + c4 * 4];
            As[c4 * 4 + 0][row] = v.x;
            As[c4 * 4 + 1][row] = v.y;
            As[c4 * 4 + 2][row] = v.z;
            As[c4 * 4 + 3][row] = v.w;
        }
#pragma unroll
        for (int r = 0; r < 2; r++) {
            int i = tid + r * 256;
            int row = i >> 5, c4 = i & 31;
            float4 v = *(const float4*)&W[(size_t)(k0 + row) * 3072 + n0 + c4 * 4];
            *(float4*)&Bs[row][c4 * 4] = v;
        }
        __syncthreads();

#pragma unroll
        for (int kk = 0; kk < 16; kk++) {
            float4 a0 = *(const float4*)&As[kk][ty * 4];
            float4 a1 = *(const float4*)&As[kk][64 + ty * 4];
            float4 b0 = *(const float4*)&Bs[kk][tx * 4];
            float4 b1 = *(const float4*)&Bs[kk][64 + tx * 4];
            float a[8] = {a0.x, a0.y, a0.z, a0.w, a1.x, a1.y, a1.z, a1.w};
            float b[8] = {b0.x, b0.y, b0.z, b0.w, b1.x, b1.y, b1.z, b1.w};
#pragma unroll
            for (int i = 0; i < 8; i++)
#pragma unroll
                for (int j = 0; j < 8; j++) acc[i][j] += a[i] * b[j];
        }
        __syncthreads();
    }

#pragma unroll
    for (int i = 0; i < 8; i++) {
        int m = m0 + ((i < 4) ? (ty * 4 + i) : (64 + ty * 4 + i - 4));
        int b = m >> 11, l = m & 2047;
#pragma unroll
        for (int jh = 0; jh < 2; jh++) {
            int n = n0 + jh * 64 + tx * 4;
            float4 v;
            v.x = acc[i][jh * 4 + 0] + bias[n + 0];
            v.y = acc[i][jh * 4 + 1] + bias[n + 1];
            v.z = acc[i][jh * 4 + 2] + bias[n + 2];
            v.w = acc[i][jh * 4 + 3] + bias[n + 3];
            int which = n >> 10;
            int nn = n & 1023;
            int h = nn >> 6, d = nn & 63;
            float* dst = (which == 0) ? g_Q : (which == 1) ? g_K : g_V;
            *(float4*)&dst[((size_t)(b * NH + h) * LL + l) * DH + d] = v;
        }
    }
}

// ---------------------------------------------------------------------------
// Attention (R8 exact): q-tile 128, 256 threads, 8x4 micro-tiles, S stored
// [k][q], separate softmax phase (2 threads/row), row_f rescale.
// Balanced at 2 blocks/SM; verified stack-frame-0.
// ---------------------------------------------------------------------------
#define QT 128              // q rows per block
#define QPAD 132            // padded q stride
#define KPAD 68             // padded k/d stride
#define ATTN_SMEM_FLOATS (64 * QPAD + 64 * KPAD + 64 * KPAD + 64 * QPAD + \
                          NBIAS + 3 * QT + 64)

__global__ __launch_bounds__(256) void attn_kernel(
    const int* __restrict__ mask, const float* __restrict__ rel_bias) {
    extern __shared__ float sm[];
    float* Qs = sm;                          // [d=64][q=128] (+pad)
    float* Ks = Qs + 64 * QPAD;              // [d=64][k=64]  (+pad)
    float* Vs = Ks + 64 * KPAD;              // [k=64][d=64]  (+pad)
    float* Ss = Vs + 64 * KPAD;              // [k=64][q=128] (+pad)  S / P
    float* bias_s = Ss + 64 * QPAD;          // 257
    float* row_m = bias_s + NBIAS;           // 128
    float* row_l = row_m + QT;               // 128
    float* row_f = row_l + QT;               // 128
    float* maskf = row_f + QT;               // 64

    const int tid = threadIdx.x;
    const int tx = tid & 15, ty = tid >> 4;  // tx: k/d quad, ty: q octet
    const int bh = blockIdx.y;
    const int b = bh / NH, h = bh % NH;
    const int q0 = blockIdx.x * QT;

    for (int i = tid; i < NBIAS; i += 256) bias_s[i] = rel_bias[h * NBIAS + i];
    if (tid < QT) { row_m[tid] = -1e30f; row_l[tid] = 0.f; }

    // Q tile transposed -> Qs[d][q], scale folded
    const float* Qg = g_Q + ((size_t)bh * LL + q0) * DH;
#pragma unroll
    for (int r = 0; r < 8; r++) {
        int i = tid + r * 256;               // 0..2047 float4s
        int q = i >> 4, d4 = i & 15;
        float4 v = *(const float4*)&Qg[q * DH + d4 * 4];
        Qs[(d4 * 4 + 0) * QPAD + q] = v.x * 0.125f;
        Qs[(d4 * 4 + 1) * QPAD + q] = v.y * 0.125f;
        Qs[(d4 * 4 + 2) * QPAD + q] = v.z * 0.125f;
        Qs[(d4 * 4 + 3) * QPAD + q] = v.w * 0.125f;
    }

    float o[8][4];
#pragma unroll
    for (int i = 0; i < 8; i++)
#pragma unroll
        for (int j = 0; j < 4; j++) o[i][j] = 0.f;

    __syncthreads();

    for (int kt = 0; kt < LL / 64; kt++) {
        const int k0 = kt * 64;
        const float* Kg = g_K + ((size_t)bh * LL + k0) * DH;
        const float* Vg = g_V + ((size_t)bh * LL + k0) * DH;
        // K transposed -> Ks[d][k]; V direct -> Vs[k][d]
#pragma unroll
        for (int r = 0; r < 4; r++) {
            int i = tid + r * 256;           // 0..1023 float4s
            int kq = i >> 4, d4 = i & 15;
            float4 v = *(const float4*)&Kg[kq * DH + d4 * 4];
            Ks[(d4 * 4 + 0) * KPAD + kq] = v.x;
            Ks[(d4 * 4 + 1) * KPAD + kq] = v.y;
            Ks[(d4 * 4 + 2) * KPAD + kq] = v.z;
            Ks[(d4 * 4 + 3) * KPAD + kq] = v.w;
            float4 w = *(const float4*)&Vg[kq * DH + d4 * 4];
            *(float4*)&Vs[kq * KPAD + d4 * 4] = w;
        }
        if (tid < 64) maskf[tid] = (mask[b * LL + k0 + tid] != 0) ? 0.f : -1e30f;
        __syncthreads();

        // ---- S = Q K^T : thread (ty,tx) -> q rows ty*8..+7, k cols tx*4..+3
        float s[8][4];
#pragma unroll
        for (int i = 0; i < 8; i++)
#pragma unroll
            for (int j = 0; j < 4; j++) s[i][j] = 0.f;
#pragma unroll
        for (int kk = 0; kk < 64; kk++) {
            float4 a0 = *(const float4*)&Qs[kk * QPAD + ty * 8];
            float4 a1 = *(const float4*)&Qs[kk * QPAD + ty * 8 + 4];
            float4 bv = *(const float4*)&Ks[kk * KPAD + tx * 4];
            float a[8] = {a0.x, a0.y, a0.z, a0.w, a1.x, a1.y, a1.z, a1.w};
            float bb[4] = {bv.x, bv.y, bv.z, bv.w};
#pragma unroll
            for (int i = 0; i < 8; i++)
#pragma unroll
                for (int j = 0; j < 4; j++) s[i][j] += a[i] * bb[j];
        }
        // store S transposed: Ss[k][q]
#pragma unroll
        for (int j = 0; j < 4; j++) {
            float* dst = &Ss[(tx * 4 + j) * QPAD + ty * 8];
            *(float4*)&dst[0] = make_float4(s[0][j], s[1][j], s[2][j], s[3][j]);
            *(float4*)&dst[4] = make_float4(s[4][j], s[5][j], s[6][j], s[7][j]);
        }
        __syncthreads();

        // ---- streaming softmax: 2 threads per q row, 32 k each ----
        {
            const int r = tid >> 1, c = tid & 1;
            const int qg = q0 + r;
            float vals[32];
            float mx = -1e30f;
#pragma unroll
            for (int u = 0; u < 32; u++) {
                const int kk = c * 32 + u;
                const int kg = k0 + kk;
                int rel = kg - qg;
                rel = rel < -MD ? -MD : (rel > MD ? MD : rel);
                float v = Ss[kk * QPAD + r] + bias_s[rel + MD] + maskf[kk];
                vals[u] = v;
                mx = fmaxf(mx, v);
            }
            mx = fmaxf(mx, __shfl_xor_sync(0xffffffffu, mx, 1));
            const float mold = row_m[r];
            const float mnew = fmaxf(mold, mx);
            float sum = 0.f;
#pragma unroll
            for (int u = 0; u < 32; u++) {
                float e = __expf(vals[u] - mnew);
                Ss[(c * 32 + u) * QPAD + r] = e;
                sum += e;
            }
            sum += __shfl_xor_sync(0xffffffffu, sum, 1);
            if (c == 0) {
                float f = __expf(mold - mnew);
                row_f[r] = f;
                row_m[r] = mnew;
                row_l[r] = row_l[r] * f + sum;
            }
        }
        __syncthreads();

        // ---- rescale O, then O += P V : P = Ss[k][q], V = Vs[k][d] ----
#pragma unroll
        for (int i = 0; i < 8; i++) {
            const float f = row_f[ty * 8 + i];
#pragma unroll
            for (int j = 0; j < 4; j++) o[i][j] *= f;
        }
#pragma unroll
        for (int kk = 0; kk < 64; kk++) {
            float4 p0 = *(const float4*)&Ss[kk * QPAD + ty * 8];
            float4 p1 = *(const float4*)&Ss[kk * QPAD + ty * 8 + 4];
            float4 vv = *(const float4*)&Vs[kk * KPAD + tx * 4];
            float p[8] = {p0.x, p0.y, p0.z, p0.w, p1.x, p1.y, p1.z, p1.w};
#pragma unroll
            for (int i = 0; i < 8; i++) {
                o[i][0] += p[i] * vv.x;
                o[i][1] += p[i] * vv.y;
                o[i][2] += p[i] * vv.z;
                o[i][3] += p[i] * vv.w;
            }
        }
        __syncthreads();   // before next tile overwrites Ks/Vs/Ss
    }

    // epilogue: normalize, write [b, l, h*64+d]
#pragma unroll
    for (int i = 0; i < 8; i++) {
        const int q = ty * 8 + i;
        const float inv = 1.f / row_l[q];
        const int qg = q0 + q;
        *(float4*)&g_AO[((size_t)b * LL + qg) * DM + h * DH + tx * 4] =
            make_float4(o[i][0] * inv, o[i][1] * inv,
                        o[i][2] * inv, o[i][3] * inv);
    }
}

// ---------------------------------------------------------------------------
// GEMM 2 (R2 exact): out = AO @ Wo + bo.
// ---------------------------------------------------------------------------
__global__ __launch_bounds__(256) void out_gemm(
    const float* __restrict__ W, const float* __restrict__ bias,
    float* __restrict__ out) {
    __shared__ float As[16][132];
    __shared__ float Bs[16][128];

    const int tid = threadIdx.x;
    const int tx = tid & 15, ty = tid >> 4;
    const int m0 = blockIdx.y * 128, n0 = blockIdx.x * 128;
    const float* A = g_AO;

    float acc[8][8];
#pragma unroll
    for (int i = 0; i < 8; i++)
#pragma unroll
        for (int j = 0; j < 8; j++) acc[i][j] = 0.f;

    for (int k0 = 0; k0 < 1024; k0 += 16) {
#pragma unroll
        for (int r = 0; r < 2; r++) {
            int i = tid + r * 256;
            int row = i >> 2, c4 = i & 3;
            float4 v = *(const float4*)&A[(size_t)(m0 + row) * 1024 + k0 + c4 * 4];
            As[c4 * 4 + 0][row] = v.x;
            As[c4 * 4 + 1][row] = v.y;
            As[c4 * 4 + 2][row] = v.z;
            As[c4 * 4 + 3][row] = v.w;
        }
#pragma unroll
        for (int r = 0; r < 2; r++) {
            int i = tid + r * 256;
            int row = i >> 5, c4 = i & 31;
            float4 v = *(const float4*)&W[(size_t)(k0 + row) * 1024 + n0 + c4 * 4];
            *(float4*)&Bs[row][c4 * 4] = v;
        }
        __syncthreads();
#pragma unroll
        for (int kk = 0; kk < 16; kk++) {
            float4 a0 = *(const float4*)&As[kk][ty * 4];
            float4 a1 = *(const float4*)&As[kk][64 + ty * 4];
            float4 b0 = *(const float4*)&Bs[kk][tx * 4];
            float4 b1 = *(const float4*)&Bs[kk][64 + tx * 4];
            float a[8] = {a0.x, a0.y, a0.z, a0.w, a1.x, a1.y, a1.z, a1.w};
            float b[8] = {b0.x, b0.y, b0.z, b0.w, b1.x, b1.y, b1.z, b1.w};
#pragma unroll
            for (int i = 0; i < 8; i++)
#pragma unroll
                for (int j = 0; j < 8; j++) acc[i][j] += a[i] * b[j];
        }
        __syncthreads();
    }

#pragma unroll
    for (int i = 0; i < 8; i++) {
        int m = m0 + ((i < 4) ? (ty * 4 + i) : (64 + ty * 4 + i - 4));
#pragma unroll
        for (int jh = 0; jh < 2; jh++) {
            int n = n0 + jh * 64 + tx * 4;
            float4 v;
            v.x = acc[i][jh * 4 + 0] + bias[n + 0];
            v.y = acc[i][jh * 4 + 1] + bias[n + 1];
            v.z = acc[i][jh * 4 + 2] + bias[n + 2];
            v.w = acc[i][jh * 4 + 3] + bias[n + 3];
            *(float4*)&out[(size_t)m * 1024 + n] = v;
        }
    }
}

// ---------------------------------------------------------------------------
extern "C" void kernel_launch(void* const* d_in, const int* in_sizes, int n_in,
                              void* d_out, int out_size) {
    const float* x    = (const float*)d_in[0];
    const int* mask   = (const int*)d_in[1];      // bool -> int32 in harness
    const float* Wqkv = (const float*)d_in[2];
    const float* bqkv = (const float*)d_in[3];
    const float* Wo   = (const float*)d_in[4];
    const float* bo   = (const float*)d_in[5];
    const float* rb   = (const float*)d_in[6];
    float* out        = (float*)d_out;

    qkv_gemm<<<dim3(3072 / 128, 8192 / 128), 256>>>(x, Wqkv, bqkv);

    const int smem_bytes = ATTN_SMEM_FLOATS * (int)sizeof(float);
    cudaFuncSetAttribute(attn_kernel,
                         cudaFuncAttributeMaxDynamicSharedMemorySize, smem_bytes);
    attn_kernel<<<dim3(LL / QT, BB * NH), 256, smem_bytes>>>(mask, rb);

    out_gemm<<<dim3(1024 / 128, 8192 / 128), 256>>>(Wo, bo, out);
}